// round 14
// baseline (speedup 1.0000x reference)
#include <cuda_runtime.h>
#include <cuda_fp16.h>
#include <math.h>
#include <stdint.h>

// ---------------- problem constants ----------------
#define B_SZ   128
#define K_SZ   256
#define M_SZ   8
#define D_SZ   128
#define NQ     (B_SZ * K_SZ)   // 32768 query rows
#define NP     (K_SZ * M_SZ)   // 2048 prototype rows

#define GAMMA_F  20.0f
#define LAMBDA_F 20.0f
#define MARGIN_F 0.05f
#define EPS_F    1e-8f

// ---------------- tile config ----------------
#define BM 128              // query rows per CTA
#define BN 128              // prototype rows per chunk (16 concepts)
#define NCHUNK (NP / BN)    // 16
#define NTHREADS 512        // 16 warps: warp_m = w>>2 (4, 32 rows), warp_n = w&3 (4, 32 cols)
#define NCTAS (NQ / BM)     // 256

// padded fp16 A-tile row stride (conflict-free ldmatrix)
#define TSTRIDE 272

#define OFF_A   0
#define OFF_RED (BM * TSTRIDE)            // 34816
#define SMEM_BYTES (OFF_RED + 2 * BM * 4) // 35840

__device__ float g_loss_sum;   // zero-init at load; reset by last CTA each call
__device__ int   g_pos_cnt;
__device__ unsigned int g_done;

// Fragment-major fp16 prototypes (written by cvt kernel each call).
// For each (chunk, ks): 2048 halves = 4 warp_n sub-blocks of 512 halves;
// each sub-block = 2×256 halves (regs b0..b3, b4..b7), lane-major 8 halves.
// reg r of lane l = permuted-row  wn*32 + 16*(r>>2) + 8*((r>>1)&1) + (l>>2),
//                   k = ks*16 + 8*(r&1) + 2*(l&3).
// Concept permutation (within a 128-row chunk): proto (c_loc, m) at row
//   (c_loc>>2)*32 + (m>>1)*8 + (c_loc&3)*2 + (m&1)
// so thread t=lane&3 of each quad owns concept warp_n*4+t's full 8-proto group.
__device__ __half P16F[NP * D_SZ + 2048];

__device__ __forceinline__ uint32_t smem_u32(const void* p) {
    uint32_t a;
    asm("{ .reg .u64 t; cvta.to.shared.u64 t, %1; cvt.u32.u64 %0, t; }" : "=r"(a) : "l"(p));
    return a;
}

__device__ __forceinline__ void ldsm_x4(uint32_t& r0, uint32_t& r1, uint32_t& r2, uint32_t& r3,
                                        uint32_t addr) {
    asm volatile("ldmatrix.sync.aligned.m8n8.x4.shared.b16 {%0,%1,%2,%3}, [%4];"
                 : "=r"(r0), "=r"(r1), "=r"(r2), "=r"(r3) : "r"(addr));
}

// fp16-accumulate HMMA: C/D = 2 b32 regs (4 halves).
__device__ __forceinline__ void mma_f16acc(uint32_t* c, uint32_t a0, uint32_t a1, uint32_t a2,
                                           uint32_t a3, uint32_t b0, uint32_t b1) {
    asm volatile(
        "mma.sync.aligned.m16n8k16.row.col.f16.f16.f16.f16 "
        "{%0,%1}, {%2,%3,%4,%5}, {%6,%7}, {%0,%1};"
        : "+r"(c[0]), "+r"(c[1])
        : "r"(a0), "r"(a1), "r"(a2), "r"(a3), "r"(b0), "r"(b1));
}

__device__ __forceinline__ uint32_t pack2h(float a, float b) {
    __half2 t = __floats2half2_rn(a, b);
    return *reinterpret_cast<uint32_t*>(&t);
}

// ---- P fp32 -> fragment-major fp16 (same layout as R11) ----
__global__ void mpc_cvt_kernel(const float* __restrict__ P) {
    int i = blockIdx.x * blockDim.x + threadIdx.x;
    if (i < NP * D_SZ / 2) {
        int u   = i & 127;
        int l   = u >> 2;         // lane
        int rr  = u & 3;          // reg within sub-block
        int blk = i >> 7;
        int sub = blk & 1;
        int wn  = (blk >> 1) & 3;
        int ks  = (blk >> 3) & 7;
        int ch  = blk >> 6;
        int S = wn * 32 + sub * 16 + (rr >> 1) * 8 + (l >> 2);
        int a = S >> 5, b = (S >> 3) & 3, d = (S >> 1) & 3, e = S & 1;
        int c_loc = a * 4 + d, m = b * 2 + e;
        int k0 = ks * 16 + (rr & 1) * 8 + (l & 3) * 2;
        float2 v = *reinterpret_cast<const float2*>(
            P + ((size_t)(ch * 128 + c_loc * 8 + m)) * D_SZ + k0);
        reinterpret_cast<uint32_t*>(P16F)[i] = pack2h(v.x, v.y);
    }
}

// one softmax group of the previous chunk's accumulators
__device__ __forceinline__ void epi_group(const uint32_t (&accP)[2][4][2], int mf, int hr,
                                          int prevCg, int ct, int rlow, int kbase,
                                          float (&denomAcc)[4], float (&simPos)[4]) {
    float Z = 0.0f, W = 0.0f;
    #pragma unroll
    for (int nf = 0; nf < 4; ++nf) {
        float2 f = __half22float2(*reinterpret_cast<const __half2*>(&accP[mf][nf][hr]));
        float ea = __expf(GAMMA_F * f.x);
        float ec = __expf(GAMMA_F * f.y);
        Z += ea + ec;
        W = fmaf(ea, f.x, W);
        W = fmaf(ec, f.y, W);
    }
    float sim = __fdividef(W, Z);
    denomAcc[2 * mf + hr] += __expf(LAMBDA_F * sim);
    int row = rlow + mf * 16 + hr * 8;
    if (prevCg + ct == kbase + row) simPos[2 * mf + hr] = sim;
}

// one chunk of MMAs into accN, with the PREVIOUS chunk's epilogue (on accP)
// interleaved into the ks stream (one group per 2 ks steps).
template <bool DO_EPI>
__device__ __forceinline__ void chunk_step(
    int chunk, const __half* __restrict__ bp, uint32_t aB0, uint32_t aB1,
    uint32_t (&accN)[2][4][2], uint32_t (&accP)[2][4][2],
    int prevCg, int ct, int rlow, int kbase,
    float (&denomAcc)[4], float (&simPos)[4])
{
    #pragma unroll
    for (int mf = 0; mf < 2; mf++)
        #pragma unroll
        for (int nf = 0; nf < 4; nf++) { accN[mf][nf][0] = 0u; accN[mf][nf][1] = 0u; }

    #pragma unroll
    for (int ks = 0; ks < 8; ++ks) {
        const __half* kp = bp + (size_t)(chunk * 8 + ks) * 2048;
        uint4 c0 = __ldg(reinterpret_cast<const uint4*>(kp));
        uint4 c1 = __ldg(reinterpret_cast<const uint4*>(kp + 256));
        const uint32_t ko = (uint32_t)ks * 32;
        uint32_t a0[4], a1[4];
        ldsm_x4(a0[0], a0[1], a0[2], a0[3], aB0 + ko);
        ldsm_x4(a1[0], a1[1], a1[2], a1[3], aB1 + ko);

        mma_f16acc(accN[0][0], a0[0], a0[1], a0[2], a0[3], c0.x, c0.y);
        mma_f16acc(accN[0][1], a0[0], a0[1], a0[2], a0[3], c0.z, c0.w);
        mma_f16acc(accN[0][2], a0[0], a0[1], a0[2], a0[3], c1.x, c1.y);
        mma_f16acc(accN[0][3], a0[0], a0[1], a0[2], a0[3], c1.z, c1.w);
        mma_f16acc(accN[1][0], a1[0], a1[1], a1[2], a1[3], c0.x, c0.y);
        mma_f16acc(accN[1][1], a1[0], a1[1], a1[2], a1[3], c0.z, c0.w);
        mma_f16acc(accN[1][2], a1[0], a1[1], a1[2], a1[3], c1.x, c1.y);
        mma_f16acc(accN[1][3], a1[0], a1[1], a1[2], a1[3], c1.z, c1.w);

        if constexpr (DO_EPI) {
            if (ks & 1) {
                const int g = ks >> 1;   // 0..3
                epi_group(accP, g >> 1, g & 1, prevCg, ct, rlow, kbase, denomAcc, simPos);
            }
        }
    }
}

__global__ __launch_bounds__(NTHREADS, 2)
void mpc_main_kernel(const float* __restrict__ V,
                     const int*   __restrict__ labels,
                     float* __restrict__ out)
{
    extern __shared__ char smem[];
    const uint32_t sb = smem_u32(smem);
    const int tid  = threadIdx.x;
    const int warp = tid >> 5;
    const int lane = tid & 31;
    const int warp_m = warp >> 2;   // 0..3 -> rows 32*warp_m
    const int warp_n = warp & 3;    // 0..3 -> cols 32*warp_n
    const int rowBase = blockIdx.x * BM;
    const int kbase   = rowBase & (K_SZ - 1);   // 0 or 128

    float* denom_s = reinterpret_cast<float*>(smem + OFF_RED);
    float* sims_s  = denom_s + BM;
    if (tid < BM) { denom_s[tid] = 0.0f; sims_s[tid] = 0.0f; }

    // ---- prologue: A tile fp16 into smem (read-only afterwards) ----
    {
        const float4* gv = reinterpret_cast<const float4*>(V + (size_t)rowBase * D_SZ);
        #pragma unroll
        for (int i = 0; i < 8; i++) {
            int linear = tid + i * NTHREADS;   // float4 index (4096 total)
            int row  = linear >> 5;
            int col4 = linear & 31;
            float4 v = __ldg(gv + linear);
            *reinterpret_cast<uint2*>(smem + OFF_A + (uint32_t)row * TSTRIDE
                                      + (uint32_t)col4 * 8) =
                make_uint2(pack2h(v.x, v.y), pack2h(v.z, v.w));
        }
    }
    __syncthreads();   // the ONLY barrier before the reduction

    // lane-invariant A ldmatrix address components
    const uint32_t aLane = (uint32_t)(warp_m * 32 + (lane & 15)) * TSTRIDE
                         + (uint32_t)(lane >> 4) * 16;
    const uint32_t aB0 = sb + OFF_A + aLane;
    const uint32_t aB1 = aB0 + 16u * TSTRIDE;

    // this thread's concept-within-chunk and rows
    const int ct   = warp_n * 4 + (lane & 3);
    const int rlow = warp_m * 32 + (lane >> 2);   // + mf*16 + hr*8

    // B fragment pointer (halves): block stride 2048, wn sub-offset 512, lane 8
    const __half* bp = P16F + warp_n * 512 + lane * 8;

    float denomAcc[4], simPos[4];   // [2*mf + hr]
    #pragma unroll
    for (int i = 0; i < 4; i++) { denomAcc[i] = 0.0f; simPos[i] = 0.0f; }

    uint32_t accA[2][4][2], accB[2][4][2];

    // chunk 0: no previous epilogue
    chunk_step<false>(0, bp, aB0, aB1, accA, accB, 0, ct, rlow, kbase, denomAcc, simPos);

    // chunks 1..14 in pairs: MMA(c) || epi(c-1)
    #pragma unroll 1
    for (int c = 1; c < 15; c += 2) {
        chunk_step<true>(c,     bp, aB0, aB1, accB, accA, (c - 1) * 16,
                         ct, rlow, kbase, denomAcc, simPos);
        chunk_step<true>(c + 1, bp, aB0, aB1, accA, accB, c * 16,
                         ct, rlow, kbase, denomAcc, simPos);
    }
    // chunk 15: MMA || epi(14)
    chunk_step<true>(15, bp, aB0, aB1, accB, accA, 14 * 16,
                     ct, rlow, kbase, denomAcc, simPos);
    // final epilogue for chunk 15
    #pragma unroll
    for (int g = 0; g < 4; ++g)
        epi_group(accB, g >> 1, g & 1, 15 * 16, ct, rlow, kbase, denomAcc, simPos);

    // ---- quad reduce (4 concepts -> per-row partials), then smem atomics ----
    #pragma unroll
    for (int o = 1; o <= 2; o <<= 1) {
        #pragma unroll
        for (int i = 0; i < 4; i++) {
            denomAcc[i] += __shfl_xor_sync(0xffffffffu, denomAcc[i], o);
            simPos[i]   += __shfl_xor_sync(0xffffffffu, simPos[i], o);
        }
    }
    if ((lane & 3) == 0) {
        #pragma unroll
        for (int mf = 0; mf < 2; ++mf) {
            int r = rlow + mf * 16;
            atomicAdd(&denom_s[r],     denomAcc[2 * mf]);
            atomicAdd(&denom_s[r + 8], denomAcc[2 * mf + 1]);
            atomicAdd(&sims_s[r],      simPos[2 * mf]);
            atomicAdd(&sims_s[r + 8],  simPos[2 * mf + 1]);
        }
    }
    __syncthreads();

    float lsum = 0.0f;
    int   lcnt = 0;
    if (tid < BM) {
        float d = denom_s[tid];
        float p = sims_s[tid];
        float loss = __logf(d + EPS_F) - LAMBDA_F * (p + MARGIN_F);
        if (labels[rowBase + tid] == 1) { lsum = loss; lcnt = 1; }
    }
    #pragma unroll
    for (int o = 16; o > 0; o >>= 1) {
        lsum += __shfl_xor_sync(0xffffffffu, lsum, o);
        lcnt += __shfl_xor_sync(0xffffffffu, lcnt, o);
    }
    __shared__ float ws[16];
    __shared__ int   wc[16];
    if (lane == 0) { ws[warp] = lsum; wc[warp] = lcnt; }
    __syncthreads();

    // ---- single-launch finalize: last CTA writes out, resets globals ----
    if (tid == 0) {
        float s = 0.0f; int n = 0;
        #pragma unroll
        for (int i = 0; i < 16; i++) { s += ws[i]; n += wc[i]; }
        atomicAdd(&g_loss_sum, s);
        atomicAdd(&g_pos_cnt, n);
        __threadfence();
        unsigned int old = atomicAdd(&g_done, 1u);
        if (old == NCTAS - 1) {
            float ts = g_loss_sum;
            int   tn = g_pos_cnt;
            out[0] = (tn > 0) ? (ts / (float)tn) : ts;
            g_loss_sum = 0.0f;
            g_pos_cnt  = 0;
            __threadfence();
            g_done = 0u;
        }
    }
}

extern "C" void kernel_launch(void* const* d_in, const int* in_sizes, int n_in,
                              void* d_out, int out_size)
{
    const float* V = nullptr;
    const int*   L = nullptr;
    const float* P = nullptr;
    for (int i = 0; i < n_in; i++) {
        if      (in_sizes[i] == NQ * D_SZ) V = (const float*)d_in[i];
        else if (in_sizes[i] == NQ)        L = (const int*)d_in[i];
        else if (in_sizes[i] == NP * D_SZ) P = (const float*)d_in[i];
    }

    cudaFuncSetAttribute(mpc_main_kernel,
                         cudaFuncAttributeMaxDynamicSharedMemorySize, SMEM_BYTES);

    const int nout = NP * D_SZ / 2;   // 131072 uint32
    mpc_cvt_kernel<<<(nout + 255) / 256, 256>>>(P);
    mpc_main_kernel<<<NCTAS, NTHREADS, SMEM_BYTES>>>(V, L, (float*)d_out);
}

// round 15
// speedup vs baseline: 1.8230x; 1.8230x over previous
#include <cuda_runtime.h>
#include <cuda_fp16.h>
#include <math.h>
#include <stdint.h>

// ---------------- problem constants ----------------
#define B_SZ   128
#define K_SZ   256
#define M_SZ   8
#define D_SZ   128
#define NQ     (B_SZ * K_SZ)   // 32768 query rows
#define NP     (K_SZ * M_SZ)   // 2048 prototype rows

#define GAMMA_F  20.0f
#define LAMBDA_F 20.0f
#define MARGIN_F 0.05f
#define EPS_F    1e-8f
#define GLOG2E   28.8539008f   // GAMMA * log2(e)

// ---------------- tile config ----------------
#define BM 128              // query rows per CTA
#define BN 128              // prototype rows per chunk (16 concepts)
#define NCHUNK (NP / BN)    // 16
#define NTHREADS 512        // 16 warps: warp_m = w>>2 (4, 32 rows), warp_n = w&3 (4, 32 cols)
#define NCTAS (NQ / BM)     // 256

// padded fp16 A-tile row stride (conflict-free ldmatrix)
#define TSTRIDE 272

#define OFF_A   0
#define OFF_RED (BM * TSTRIDE)            // 34816
#define SMEM_BYTES (OFF_RED + 2 * BM * 4) // 35840

__device__ float g_loss_sum;   // zero-init at load; reset by last CTA each call
__device__ int   g_pos_cnt;
__device__ unsigned int g_done;

// Fragment-major fp16 prototypes (written by cvt kernel each call).
// For each (chunk, ks): 2048 halves = 4 warp_n sub-blocks of 512 halves;
// each sub-block = 2×256 halves (regs b0..b3, b4..b7), lane-major 8 halves.
// reg r of lane l = permuted-row  wn*32 + 16*(r>>2) + 8*((r>>1)&1) + (l>>2),
//                   k = ks*16 + 8*(r&1) + 2*(l&3).
// Concept permutation (within a 128-row chunk): proto (c_loc, m) at row
//   (c_loc>>2)*32 + (m>>1)*8 + (c_loc&3)*2 + (m&1)
// so thread t=lane&3 of each quad owns concept warp_n*4+t's full 8-proto group.
// +2048 halves pad: last-iteration prefetch over-read lands in-bounds.
__device__ __half P16F[NP * D_SZ + 2048];

__device__ __forceinline__ uint32_t smem_u32(const void* p) {
    uint32_t a;
    asm("{ .reg .u64 t; cvta.to.shared.u64 t, %1; cvt.u32.u64 %0, t; }" : "=r"(a) : "l"(p));
    return a;
}

__device__ __forceinline__ void ldsm_x4(uint32_t& r0, uint32_t& r1, uint32_t& r2, uint32_t& r3,
                                        uint32_t addr) {
    asm volatile("ldmatrix.sync.aligned.m8n8.x4.shared.b16 {%0,%1,%2,%3}, [%4];"
                 : "=r"(r0), "=r"(r1), "=r"(r2), "=r"(r3) : "r"(addr));
}

// fp16-accumulate HMMA: C/D = 2 b32 regs (4 halves).
__device__ __forceinline__ void mma_f16acc(uint32_t* c, uint32_t a0, uint32_t a1, uint32_t a2,
                                           uint32_t a3, uint32_t b0, uint32_t b1) {
    asm volatile(
        "mma.sync.aligned.m16n8k16.row.col.f16.f16.f16.f16 "
        "{%0,%1}, {%2,%3,%4,%5}, {%6,%7}, {%0,%1};"
        : "+r"(c[0]), "+r"(c[1])
        : "r"(a0), "r"(a1), "r"(a2), "r"(a3), "r"(b0), "r"(b1));
}

__device__ __forceinline__ uint32_t pack2h(float a, float b) {
    __half2 t = __floats2half2_rn(a, b);
    return *reinterpret_cast<uint32_t*>(&t);
}

// ---- P fp32 -> fragment-major fp16 (same layout as R11) ----
__global__ void mpc_cvt_kernel(const float* __restrict__ P) {
    int i = blockIdx.x * blockDim.x + threadIdx.x;
    if (i < NP * D_SZ / 2) {
        int u   = i & 127;
        int l   = u >> 2;         // lane
        int rr  = u & 3;          // reg within sub-block
        int blk = i >> 7;
        int sub = blk & 1;
        int wn  = (blk >> 1) & 3;
        int ks  = (blk >> 3) & 7;
        int ch  = blk >> 6;
        int S = wn * 32 + sub * 16 + (rr >> 1) * 8 + (l >> 2);
        int a = S >> 5, b = (S >> 3) & 3, d = (S >> 1) & 3, e = S & 1;
        int c_loc = a * 4 + d, m = b * 2 + e;
        int k0 = ks * 16 + (rr & 1) * 8 + (l & 3) * 2;
        float2 v = *reinterpret_cast<const float2*>(
            P + ((size_t)(ch * 128 + c_loc * 8 + m)) * D_SZ + k0);
        reinterpret_cast<uint32_t*>(P16F)[i] = pack2h(v.x, v.y);
    }
}

__global__ __launch_bounds__(NTHREADS, 2)
void mpc_main_kernel(const float* __restrict__ V,
                     const int*   __restrict__ labels,
                     float* __restrict__ out)
{
    extern __shared__ char smem[];
    const uint32_t sb = smem_u32(smem);
    const int tid  = threadIdx.x;
    const int warp = tid >> 5;
    const int lane = tid & 31;
    const int warp_m = warp >> 2;   // 0..3 -> rows 32*warp_m
    const int warp_n = warp & 3;    // 0..3 -> cols 32*warp_n
    const int rowBase = blockIdx.x * BM;
    const int kbase   = rowBase & (K_SZ - 1);   // 0 or 128

    float* denom_s = reinterpret_cast<float*>(smem + OFF_RED);
    float* sims_s  = denom_s + BM;
    if (tid < BM) { denom_s[tid] = 0.0f; sims_s[tid] = 0.0f; }

    // ---- prologue: A tile fp16 into smem (read-only afterwards) ----
    {
        const float4* gv = reinterpret_cast<const float4*>(V + (size_t)rowBase * D_SZ);
        #pragma unroll
        for (int i = 0; i < 8; i++) {
            int linear = tid + i * NTHREADS;   // float4 index (4096 total)
            int row  = linear >> 5;
            int col4 = linear & 31;
            float4 v = __ldg(gv + linear);
            *reinterpret_cast<uint2*>(smem + OFF_A + (uint32_t)row * TSTRIDE
                                      + (uint32_t)col4 * 8) =
                make_uint2(pack2h(v.x, v.y), pack2h(v.z, v.w));
        }
    }
    __syncthreads();   // the ONLY barrier before the reduction

    // lane-invariant A ldmatrix address components
    const uint32_t aLane = (uint32_t)(warp_m * 32 + (lane & 15)) * TSTRIDE
                         + (uint32_t)(lane >> 4) * 16;
    const uint32_t aB0 = sb + OFF_A + aLane;
    const uint32_t aB1 = aB0 + 16u * TSTRIDE;

    // this thread's concept-within-chunk and rows
    const int ct    = warp_n * 4 + (lane & 3);
    const int rlow  = warp_m * 32 + (lane >> 2);   // + mf*16 + hr*8

    // B fragment pointer (halves): block stride 2048, wn sub-offset 512, lane 8
    const __half* bp = P16F + warp_n * 512 + lane * 8;

    float denomAcc[4], simPos[4];   // [2*mf + hr]
    #pragma unroll
    for (int i = 0; i < 4; i++) { denomAcc[i] = 0.0f; simPos[i] = 0.0f; }

    const __half2 K2 = __float2half2_rn(GLOG2E);

    // prime first ks block
    uint4 c0 = __ldg(reinterpret_cast<const uint4*>(bp));
    uint4 c1 = __ldg(reinterpret_cast<const uint4*>(bp + 256));

    #pragma unroll 1
    for (int chunk = 0; chunk < NCHUNK; ++chunk) {
        // fp16x2 accumulators: acc[mf][nf][hr]
        uint32_t acc[2][4][2];
        #pragma unroll
        for (int mf = 0; mf < 2; mf++)
            #pragma unroll
            for (int nf = 0; nf < 4; nf++) {
                acc[mf][nf][0] = 0u;
                acc[mf][nf][1] = 0u;
            }

        #pragma unroll
        for (int ks = 0; ks < 8; ++ks) {
            // prefetch next ks-block (pad absorbs final over-read)
            const __half* np_ = bp + (size_t)(chunk * 8 + ks + 1) * 2048;
            uint4 n0 = __ldg(reinterpret_cast<const uint4*>(np_));
            uint4 n1 = __ldg(reinterpret_cast<const uint4*>(np_ + 256));

            const uint32_t ko = (uint32_t)ks * 32;
            uint32_t a0[4], a1[4];
            ldsm_x4(a0[0], a0[1], a0[2], a0[3], aB0 + ko);
            ldsm_x4(a1[0], a1[1], a1[2], a1[3], aB1 + ko);

            mma_f16acc(acc[0][0], a0[0], a0[1], a0[2], a0[3], c0.x, c0.y);
            mma_f16acc(acc[0][1], a0[0], a0[1], a0[2], a0[3], c0.z, c0.w);
            mma_f16acc(acc[0][2], a0[0], a0[1], a0[2], a0[3], c1.x, c1.y);
            mma_f16acc(acc[0][3], a0[0], a0[1], a0[2], a0[3], c1.z, c1.w);
            mma_f16acc(acc[1][0], a1[0], a1[1], a1[2], a1[3], c0.x, c0.y);
            mma_f16acc(acc[1][1], a1[0], a1[1], a1[2], a1[3], c0.z, c0.w);
            mma_f16acc(acc[1][2], a1[0], a1[1], a1[2], a1[3], c1.x, c1.y);
            mma_f16acc(acc[1][3], a1[0], a1[1], a1[2], a1[3], c1.z, c1.w);

            c0 = n0;
            c1 = n1;
        }

        // ---- register-local half2 epilogue (no barriers, no shuffles) ----
        const int cg = chunk * 16 + ct;   // global concept this thread owns
        #pragma unroll
        for (int mf = 0; mf < 2; ++mf) {
            #pragma unroll
            for (int hr = 0; hr < 2; ++hr) {
                __half2 h0 = *reinterpret_cast<const __half2*>(&acc[mf][0][hr]);
                __half2 h1 = *reinterpret_cast<const __half2*>(&acc[mf][1][hr]);
                __half2 h2 = *reinterpret_cast<const __half2*>(&acc[mf][2][hr]);
                __half2 h3 = *reinterpret_cast<const __half2*>(&acc[mf][3][hr]);

                // group max (shift-invariant softmax; keeps exps <= 1)
                __half2 mx2 = __hmax2(__hmax2(h0, h1), __hmax2(h2, h3));
                __half  mx  = __hmax(__low2half(mx2), __high2half(mx2));
                __half2 mxx = __half2half2(mx);

                // e_i = exp2(K * (s_i - mx))  -- one MUFU per 2 protos
                __half2 e0 = h2exp2(__hmul2(__hsub2(h0, mxx), K2));
                __half2 e1 = h2exp2(__hmul2(__hsub2(h1, mxx), K2));
                __half2 e2 = h2exp2(__hmul2(__hsub2(h2, mxx), K2));
                __half2 e3 = h2exp2(__hmul2(__hsub2(h3, mxx), K2));

                __half2 Z2 = __hadd2(__hadd2(e0, e1), __hadd2(e2, e3));
                __half2 W2 = __hfma2(e0, h0,
                             __hfma2(e1, h1,
                             __hfma2(e2, h2, __hmul2(e3, h3))));

                float Zf = __low2float(Z2) + __high2float(Z2);
                float Wf = __low2float(W2) + __high2float(W2);

                float sim = __fdividef(Wf, Zf);
                denomAcc[2 * mf + hr] += __expf(LAMBDA_F * sim);
                int row = rlow + mf * 16 + hr * 8;
                if (cg == kbase + row) simPos[2 * mf + hr] = sim;
            }
        }
    }

    // ---- quad reduce (4 concepts -> per-row partials), then smem atomics ----
    #pragma unroll
    for (int o = 1; o <= 2; o <<= 1) {
        #pragma unroll
        for (int i = 0; i < 4; i++) {
            denomAcc[i] += __shfl_xor_sync(0xffffffffu, denomAcc[i], o);
            simPos[i]   += __shfl_xor_sync(0xffffffffu, simPos[i], o);
        }
    }
    if ((lane & 3) == 0) {
        #pragma unroll
        for (int mf = 0; mf < 2; ++mf) {
            int r = rlow + mf * 16;
            atomicAdd(&denom_s[r],     denomAcc[2 * mf]);
            atomicAdd(&denom_s[r + 8], denomAcc[2 * mf + 1]);
            atomicAdd(&sims_s[r],      simPos[2 * mf]);
            atomicAdd(&sims_s[r + 8],  simPos[2 * mf + 1]);
        }
    }
    __syncthreads();

    float lsum = 0.0f;
    int   lcnt = 0;
    if (tid < BM) {
        float d = denom_s[tid];
        float p = sims_s[tid];
        float loss = __logf(d + EPS_F) - LAMBDA_F * (p + MARGIN_F);
        if (labels[rowBase + tid] == 1) { lsum = loss; lcnt = 1; }
    }
    #pragma unroll
    for (int o = 16; o > 0; o >>= 1) {
        lsum += __shfl_xor_sync(0xffffffffu, lsum, o);
        lcnt += __shfl_xor_sync(0xffffffffu, lcnt, o);
    }
    __shared__ float ws[16];
    __shared__ int   wc[16];
    if (lane == 0) { ws[warp] = lsum; wc[warp] = lcnt; }
    __syncthreads();

    // ---- single-launch finalize: last CTA writes out, resets globals ----
    if (tid == 0) {
        float s = 0.0f; int n = 0;
        #pragma unroll
        for (int i = 0; i < 16; i++) { s += ws[i]; n += wc[i]; }
        atomicAdd(&g_loss_sum, s);
        atomicAdd(&g_pos_cnt, n);
        __threadfence();
        unsigned int old = atomicAdd(&g_done, 1u);
        if (old == NCTAS - 1) {
            float ts = g_loss_sum;
            int   tn = g_pos_cnt;
            out[0] = (tn > 0) ? (ts / (float)tn) : ts;
            g_loss_sum = 0.0f;
            g_pos_cnt  = 0;
            __threadfence();
            g_done = 0u;
        }
    }
}

extern "C" void kernel_launch(void* const* d_in, const int* in_sizes, int n_in,
                              void* d_out, int out_size)
{
    const float* V = nullptr;
    const int*   L = nullptr;
    const float* P = nullptr;
    for (int i = 0; i < n_in; i++) {
        if      (in_sizes[i] == NQ * D_SZ) V = (const float*)d_in[i];
        else if (in_sizes[i] == NQ)        L = (const int*)d_in[i];
        else if (in_sizes[i] == NP * D_SZ) P = (const float*)d_in[i];
    }

    cudaFuncSetAttribute(mpc_main_kernel,
                         cudaFuncAttributeMaxDynamicSharedMemorySize, SMEM_BYTES);

    const int nout = NP * D_SZ / 2;   // 131072 uint32
    mpc_cvt_kernel<<<(nout + 255) / 256, 256>>>(P);
    mpc_main_kernel<<<NCTAS, NTHREADS, SMEM_BYTES>>>(V, L, (float*)d_out);
}